// round 2
// baseline (speedup 1.0000x reference)
#include <cuda_runtime.h>
#include <cstdint>
#include <math.h>

#define B_   32
#define N_   3136
#define C_   384
#define H_   8
#define HD_  48
#define NT_  196
#define EPS_ 1e-6f
#define SCALE_ 0.14433756729740643f   /* 1/sqrt(48) */

typedef unsigned long long ull;

// ---------------------------------------------------------------------------
// Scratch: one big static device buffer (no runtime allocation).
// Kernels reference it directly (no cudaGetSymbolAddress in kernel_launch).
// ---------------------------------------------------------------------------
#define XN_OFF   ((size_t)0)
#define KV_OFF   (XN_OFF  + (size_t)B_*N_*C_)
#define QC1_OFF  (KV_OFF  + (size_t)B_*N_*2*C_)
#define HB_OFF   (QC1_OFF + (size_t)B_*NT_*C_)
#define QC2_OFF  (HB_OFF  + (size_t)B_*NT_*2*C_)
#define AV_OFF   (QC2_OFF + (size_t)B_*NT_*C_)
#define CENT_OFF (AV_OFF  + (size_t)B_*NT_*C_)
#define TOTAL_F  (CENT_OFF + (size_t)B_*NT_)

__device__ __align__(128) float g_scratch[TOTAL_F];

#define G_XN   (g_scratch + XN_OFF)
#define G_KV   (g_scratch + KV_OFF)
#define G_QC1  (g_scratch + QC1_OFF)
#define G_HB   (g_scratch + HB_OFF)
#define G_QC2  (g_scratch + QC2_OFF)
#define G_AV   (g_scratch + AV_OFF)
#define G_CENT ((int*)(g_scratch + CENT_OFF))

// ---------------------------------------------------------------------------
// f32x2 packed helpers (Blackwell: doubles fp32 FMA throughput)
// ---------------------------------------------------------------------------
__device__ __forceinline__ ull pack2(float x, float y) {
    ull r; asm("mov.b64 %0, {%1,%2};" : "=l"(r) : "f"(x), "f"(y)); return r;
}
__device__ __forceinline__ float2 unpack2(ull v) {
    float2 f; asm("mov.b64 {%0,%1}, %2;" : "=f"(f.x), "=f"(f.y) : "l"(v)); return f;
}
__device__ __forceinline__ void fma2(ull& d, ull a, ull b) {
    asm("fma.rn.f32x2 %0, %1, %2, %0;" : "+l"(d) : "l"(a), "l"(b));
}

__device__ __forceinline__ float gelu_f(float x) {
    return 0.5f * x * (1.0f + erff(x * 0.70710678118654752f));
}

// ---------------------------------------------------------------------------
// K0: LayerNorm. One block per row (b*N+n), 128 threads, 3 elems/thread.
// ---------------------------------------------------------------------------
__global__ void ln_kernel(const float* __restrict__ x,
                          const float* __restrict__ w,
                          const float* __restrict__ b) {
    int row = blockIdx.x;
    const float* xr = x + (size_t)row * C_;
    int tid = threadIdx.x;
    float v[3];
    float s = 0.f, sq = 0.f;
#pragma unroll
    for (int i = 0; i < 3; i++) {
        v[i] = xr[tid + 128 * i];
        s += v[i]; sq += v[i] * v[i];
    }
#pragma unroll
    for (int o = 16; o; o >>= 1) {
        s  += __shfl_xor_sync(0xffffffffu, s, o);
        sq += __shfl_xor_sync(0xffffffffu, sq, o);
    }
    __shared__ float ss[4], ssq[4];
    if ((tid & 31) == 0) { ss[tid >> 5] = s; ssq[tid >> 5] = sq; }
    __syncthreads();
    s  = ss[0] + ss[1] + ss[2] + ss[3];
    sq = ssq[0] + ssq[1] + ssq[2] + ssq[3];
    float mu = s * (1.0f / C_);
    float var = sq * (1.0f / C_) - mu * mu;
    float rstd = rsqrtf(var + EPS_);
    float* orow = G_XN + (size_t)row * C_;
#pragma unroll
    for (int i = 0; i < 3; i++) {
        int c = tid + 128 * i;
        orow[c] = (v[i] - mu) * rstd * w[c] + b[c];
    }
}

// ---------------------------------------------------------------------------
// Generic SIMT GEMM: C[M,Nn] = A[M,K] @ W[Nn,K]^T (+bias)(+gelu)
// BM=128, BN=64, BK=16, 256 threads, 8x4 microtile via f32x2.
// ---------------------------------------------------------------------------
#define BM 128
#define BN 64
#define BK 16

__global__ __launch_bounds__(256)
void gemm_kernel(const float* __restrict__ A, const float* __restrict__ W,
                 const float* __restrict__ bias, float* __restrict__ Cm,
                 int M, int Nn, int K, int epi) {
    __shared__ __align__(16) float As[BK][BM];
    __shared__ __align__(16) float Bs[BK][BN];
    int tid = threadIdx.x;
    int tx = tid & 15, ty = tid >> 4;
    int m0 = blockIdx.y * BM, n0 = blockIdx.x * BN;

    ull acc[8][2];
#pragma unroll
    for (int i = 0; i < 8; i++) { acc[i][0] = 0ull; acc[i][1] = 0ull; }

    int ar = tid >> 2;
    int ac = (tid & 3) * 4;

    for (int k0 = 0; k0 < K; k0 += BK) {
#pragma unroll
        for (int i = 0; i < 2; i++) {
            int r = ar + i * 64;
            float4 a4 = *(const float4*)(A + (size_t)(m0 + r) * K + k0 + ac);
            As[ac + 0][r] = a4.x; As[ac + 1][r] = a4.y;
            As[ac + 2][r] = a4.z; As[ac + 3][r] = a4.w;
        }
        {
            int r = tid >> 2;   // 0..63
            float4 w4 = *(const float4*)(W + (size_t)(n0 + r) * K + k0 + ac);
            Bs[ac + 0][r] = w4.x; Bs[ac + 1][r] = w4.y;
            Bs[ac + 2][r] = w4.z; Bs[ac + 3][r] = w4.w;
        }
        __syncthreads();
#pragma unroll
        for (int kk = 0; kk < BK; kk++) {
            float4 b4 = *(const float4*)&Bs[kk][tx * 4];
            ull b0 = pack2(b4.x, b4.y);
            ull b1 = pack2(b4.z, b4.w);
#pragma unroll
            for (int i = 0; i < 8; i++) {
                float a = As[kk][ty * 8 + i];
                ull ap = pack2(a, a);
                fma2(acc[i][0], ap, b0);
                fma2(acc[i][1], ap, b1);
            }
        }
        __syncthreads();
    }

    int gn = n0 + tx * 4;
    float bv[4] = {0.f, 0.f, 0.f, 0.f};
    if (bias) {
        bv[0] = bias[gn + 0]; bv[1] = bias[gn + 1];
        bv[2] = bias[gn + 2]; bv[3] = bias[gn + 3];
    }
#pragma unroll
    for (int i = 0; i < 8; i++) {
        int gm = m0 + ty * 8 + i;
        float2 c0 = unpack2(acc[i][0]);
        float2 c1 = unpack2(acc[i][1]);
        float4 o4;
        o4.x = c0.x + bv[0]; o4.y = c0.y + bv[1];
        o4.z = c1.x + bv[2]; o4.w = c1.y + bv[3];
        if (epi == 1) {
            o4.x = gelu_f(o4.x); o4.y = gelu_f(o4.y);
            o4.z = gelu_f(o4.z); o4.w = gelu_f(o4.w);
        }
        *(float4*)(Cm + (size_t)gm * Nn + gn) = o4;
    }
}

// ---------------------------------------------------------------------------
// K2: attn1 + q_cond1. One block per (b,h). Stage q/k_sub/v_sub in dyn smem.
// ---------------------------------------------------------------------------
#define ATTN1_SMEM (3 * NT_ * HD_ * 4)   /* 112896 bytes */

__global__ __launch_bounds__(256)
void attn1_kernel(const float* __restrict__ qg, const int* __restrict__ idx_sub) {
    extern __shared__ float sh[];
    float* qs = sh;
    float* ks = sh + NT_ * HD_;
    float* vs = sh + 2 * NT_ * HD_;
    int b = blockIdx.x >> 3;
    int h = blockIdx.x & 7;
    int tid = threadIdx.x;
    const float* kv = G_KV;

    for (int i = tid; i < NT_ * HD_; i += 256) {
        int n = i / HD_, d = i % HD_;
        qs[i] = qg[((size_t)n * H_ + h) * HD_ + d];
        int src = idx_sub[n];
        const float* kvrow = kv + ((size_t)b * N_ + src) * (2 * C_) + h * HD_ + d;
        ks[i] = kvrow[0];
        vs[i] = kvrow[C_];
    }
    __syncthreads();

    int m = tid;
    if (m < NT_) {
        float sc[NT_];
        float mx = -1e30f;
        const float* qm = qs + m * HD_;
        for (int n = 0; n < NT_; n++) {
            const float* kn = ks + n * HD_;
            float s = 0.f;
#pragma unroll
            for (int d = 0; d < HD_; d++) s += qm[d] * kn[d];
            s *= SCALE_;
            sc[n] = s;
            mx = fmaxf(mx, s);
        }
        float sum = 0.f;
        for (int n = 0; n < NT_; n++) {
            float e = expf(sc[n] - mx);
            sc[n] = e; sum += e;
        }
        float inv = 1.0f / sum;
        float accv[HD_];
#pragma unroll
        for (int d = 0; d < HD_; d++) accv[d] = 0.f;
        for (int n = 0; n < NT_; n++) {
            float wgt = sc[n];
            const float* vn = vs + n * HD_;
#pragma unroll
            for (int d = 0; d < HD_; d++) accv[d] += wgt * vn[d];
        }
        float* orow = G_QC1 + ((size_t)b * NT_ + m) * C_ + h * HD_;
#pragma unroll
        for (int d = 0; d < HD_; d++) orow[d] = accv[d] * inv;
    }
}

// ---------------------------------------------------------------------------
// K5: attn2 mean-over-heads + argmax. mean over heads = (1/8)*full-384 dot;
// constant positive scale preserves argmax -> compute full-row dots.
// First-index tie rule preserved (strict >, ascending n).
// ---------------------------------------------------------------------------
#define MCH 7
__global__ __launch_bounds__(256)
void attn2_kernel(const int* __restrict__ idxs) {
    int b = blockIdx.x / 28;
    int m0 = (blockIdx.x % 28) * MCH;
    __shared__ float qsh[MCH * C_];
    __shared__ float krow[C_];
    __shared__ int sIdxs[NT_];
    int tid = threadIdx.x;
    const float* kv = G_KV;
    for (int i = tid; i < MCH * C_; i += 256)
        qsh[i] = G_QC2[((size_t)b * NT_ + m0) * C_ + i];
    for (int i = tid; i < NT_; i += 256) sIdxs[i] = idxs[i];
    int warp = tid >> 5, lane = tid & 31;
    float best = -1e30f;
    int bestn = 0;
    __syncthreads();
    for (int n = 0; n < NT_; n++) {
        __syncthreads();
        for (int i = tid; i < C_; i += 256)
            krow[i] = kv[((size_t)b * N_ + sIdxs[n]) * (2 * C_) + i];
        __syncthreads();
        if (warp < MCH) {
            const float* qm = qsh + warp * C_;
            float p = 0.f;
#pragma unroll
            for (int j = 0; j < 12; j++) p += qm[lane + 32 * j] * krow[lane + 32 * j];
#pragma unroll
            for (int o = 16; o; o >>= 1) p += __shfl_xor_sync(0xffffffffu, p, o);
            if (p > best) { best = p; bestn = n; }
        }
    }
    if (warp < MCH && lane == 0)
        G_CENT[(size_t)b * NT_ + m0 + warp] = sIdxs[bestn];
}

// ---------------------------------------------------------------------------
// K6: masked attn3 (sparse). exp(NEG-shifted) underflows to exact 0 in f32,
// so softmax runs only over the deduped adjusted-index set (bitmap over N).
// Block per (b,m); 8 warps = 8 heads.
// ---------------------------------------------------------------------------
__global__ __launch_bounds__(256)
void attn3_kernel() {
    int bm = blockIdx.x;
    int b = bm / NT_;
    __shared__ unsigned int bmap[N_ / 32];
    __shared__ int sIdx[169];
    __shared__ int cnt;
    __shared__ float sQ[C_];
    __shared__ float sS[H_][169];
    int tid = threadIdx.x;
    const float* kv = G_KV;
    if (tid < N_ / 32) bmap[tid] = 0u;
    if (tid == 0) cnt = 0;
    __syncthreads();
    int ci = G_CENT[bm];
    if (tid < 169) {
        int row = tid / 13 - 6;
        int col = tid % 13 - 6;
        int adj = ci + (col - 56 * row);
        adj = max(0, min(N_ - 1, adj));
        atomicOr(&bmap[adj >> 5], 1u << (adj & 31));
    }
    for (int i = tid; i < C_; i += 256)
        sQ[i] = G_QC2[(size_t)bm * C_ + i] * SCALE_;
    __syncthreads();
    if (tid < N_ / 32) {
        unsigned int w = bmap[tid];
        if (w) {
            int base = atomicAdd(&cnt, __popc(w));
            int off = 0;
            while (w) {
                int bit = __ffs(w) - 1;
                w &= w - 1;
                sIdx[base + off] = (tid << 5) + bit;
                off++;
            }
        }
    }
    __syncthreads();
    int count = cnt;
    int h = tid >> 5, lane = tid & 31;
    const float* qh = sQ + h * HD_;
    float mx = -1e30f;
    for (int e = 0; e < count; e++) {
        const float* kr = kv + ((size_t)b * N_ + sIdx[e]) * (2 * C_) + h * HD_;
        float p = kr[lane] * qh[lane];
        if (lane < 16) p += kr[lane + 32] * qh[lane + 32];
#pragma unroll
        for (int o = 16; o; o >>= 1) p += __shfl_xor_sync(0xffffffffu, p, o);
        if (lane == 0) sS[h][e] = p;
        mx = fmaxf(mx, p);
    }
    __syncwarp();
    float sum = 0.f;
    for (int e = lane; e < count; e += 32) {
        float ee = expf(sS[h][e] - mx);
        sS[h][e] = ee;
        sum += ee;
    }
#pragma unroll
    for (int o = 16; o; o >>= 1) sum += __shfl_xor_sync(0xffffffffu, sum, o);
    float inv = 1.0f / sum;
    __syncwarp();
    float a0 = 0.f, a1 = 0.f;
    for (int e = 0; e < count; e++) {
        float wgt = sS[h][e];
        const float* vr = kv + ((size_t)b * N_ + sIdx[e]) * (2 * C_) + C_ + h * HD_;
        a0 += wgt * vr[lane];
        if (lane < 16) a1 += wgt * vr[lane + 32];
    }
    float* orow = G_AV + (size_t)bm * C_ + h * HD_;
    orow[lane] = a0 * inv;
    if (lane < 16) orow[lane + 32] = a1 * inv;
}

// ---------------------------------------------------------------------------
// Launch: kernel launches ONLY (max capture safety).
// ---------------------------------------------------------------------------
static bool g_attr_set = false;

extern "C" void kernel_launch(void* const* d_in, const int* in_sizes, int n_in,
                              void* d_out, int out_size) {
    const float* x      = (const float*)d_in[0];
    const float* q      = (const float*)d_in[1];
    const float* kv_w   = (const float*)d_in[2];
    const float* proj_w = (const float*)d_in[3];
    const float* proj_b = (const float*)d_in[4];
    const float* ln_w   = (const float*)d_in[5];
    const float* ln_b   = (const float*)d_in[6];
    const float* fc1_w  = (const float*)d_in[7];
    const float* fc1_b  = (const float*)d_in[8];
    const float* fc2_w  = (const float*)d_in[9];
    const float* fc2_b  = (const float*)d_in[10];
    const int* idx_sub  = (const int*)d_in[11];
    const int* idxs     = (const int*)d_in[12];
    float* out = (float*)d_out;

    cudaFuncSetAttribute(attn1_kernel,
                         cudaFuncAttributeMaxDynamicSharedMemorySize, ATTN1_SMEM);

    float* xn  = nullptr;  // kernels use G_* directly; host passes raw in/out only
    (void)xn;

    // K0: LayerNorm -> G_XN
    ln_kernel<<<B_ * N_, 128>>>(x, ln_w, ln_b);

    // K1: KV projection (dominant GEMM, fp32-exact for argmax safety)
    // A = G_XN, C = G_KV ; pass device-global addresses via kernel that
    // dereferences them itself is not possible for generic gemm, so we use a
    // tiny trampoline: gemm reads A/W/C as raw pointers; for scratch operands
    // we launch through wrapper kernels below.
    {
        dim3 g(2 * C_ / BN, (B_ * N_) / BM);
        // A and C live in g_scratch; obtain their device addresses legally by
        // passing the symbol through a __device__-linkage constant: the symbol
        // g_scratch has the same address in host-launch parameter space when
        // taken inside device code. We therefore launch a small adapter.
        extern __global__ void gemm_xn_kv(const float*);
        gemm_xn_kv<<<g, 256>>>(kv_w);
    }

    // K2: attn1 -> G_QC1
    attn1_kernel<<<B_ * H_, 256, ATTN1_SMEM>>>(q, idx_sub);

    // K3: fc1 + gelu -> G_HB
    {
        dim3 g(2 * C_ / BN, (B_ * NT_) / BM);
        extern __global__ void gemm_qc1_hb(const float*, const float*);
        gemm_qc1_hb<<<g, 256>>>(fc1_w, fc1_b);
    }
    // K4: fc2 -> G_QC2
    {
        dim3 g(C_ / BN, (B_ * NT_) / BM);
        extern __global__ void gemm_hb_qc2(const float*, const float*);
        gemm_hb_qc2<<<g, 256>>>(fc2_w, fc2_b);
    }

    // K5: attn2 + argmax -> G_CENT
    attn2_kernel<<<B_ * 28, 256>>>(idxs);

    // K6: sparse masked attn3 -> G_AV
    attn3_kernel<<<B_ * NT_, 256>>>();

    // K7: output projection -> d_out
    {
        dim3 g(C_ / BN, (B_ * NT_) / BM);
        extern __global__ void gemm_av_out(const float*, const float*, float*);
        gemm_av_out<<<g, 256>>>(proj_w, proj_b, out);
    }
    (void)g_attr_set;
}

// ---------------------------------------------------------------------------
// GEMM adapters: bind scratch operands inside device code (no host-side
// symbol-address query needed). They share the gemm body via a device func.
// ---------------------------------------------------------------------------
__device__ __forceinline__
void gemm_body(const float* __restrict__ A, const float* __restrict__ W,
               const float* __restrict__ bias, float* __restrict__ Cm,
               int M, int Nn, int K, int epi) {
    __shared__ __align__(16) float As[BK][BM];
    __shared__ __align__(16) float Bs[BK][BN];
    int tid = threadIdx.x;
    int tx = tid & 15, ty = tid >> 4;
    int m0 = blockIdx.y * BM, n0 = blockIdx.x * BN;

    ull acc[8][2];
#pragma unroll
    for (int i = 0; i < 8; i++) { acc[i][0] = 0ull; acc[i][1] = 0ull; }

    int ar = tid >> 2;
    int ac = (tid & 3) * 4;

    for (int k0 = 0; k0 < K; k0 += BK) {
#pragma unroll
        for (int i = 0; i < 2; i++) {
            int r = ar + i * 64;
            float4 a4 = *(const float4*)(A + (size_t)(m0 + r) * K + k0 + ac);
            As[ac + 0][r] = a4.x; As[ac + 1][r] = a4.y;
            As[ac + 2][r] = a4.z; As[ac + 3][r] = a4.w;
        }
        {
            int r = tid >> 2;
            float4 w4 = *(const float4*)(W + (size_t)(n0 + r) * K + k0 + ac);
            Bs[ac + 0][r] = w4.x; Bs[ac + 1][r] = w4.y;
            Bs[ac + 2][r] = w4.z; Bs[ac + 3][r] = w4.w;
        }
        __syncthreads();
#pragma unroll
        for (int kk = 0; kk < BK; kk++) {
            float4 b4 = *(const float4*)&Bs[kk][tx * 4];
            ull b0 = pack2(b4.x, b4.y);
            ull b1 = pack2(b4.z, b4.w);
#pragma unroll
            for (int i = 0; i < 8; i++) {
                float a = As[kk][ty * 8 + i];
                ull ap = pack2(a, a);
                fma2(acc[i][0], ap, b0);
                fma2(acc[i][1], ap, b1);
            }
        }
        __syncthreads();
    }

    int gn = n0 + tx * 4;
    float bv[4] = {0.f, 0.f, 0.f, 0.f};
    if (bias) {
        bv[0] = bias[gn + 0]; bv[1] = bias[gn + 1];
        bv[2] = bias[gn + 2]; bv[3] = bias[gn + 3];
    }
#pragma unroll
    for (int i = 0; i < 8; i++) {
        int gm = m0 + ty * 8 + i;
        float2 c0 = unpack2(acc[i][0]);
        float2 c1 = unpack2(acc[i][1]);
        float4 o4;
        o4.x = c0.x + bv[0]; o4.y = c0.y + bv[1];
        o4.z = c1.x + bv[2]; o4.w = c1.y + bv[3];
        if (epi == 1) {
            o4.x = gelu_f(o4.x); o4.y = gelu_f(o4.y);
            o4.z = gelu_f(o4.z); o4.w = gelu_f(o4.w);
        }
        *(float4*)(Cm + (size_t)gm * Nn + gn) = o4;
    }
}

__global__ __launch_bounds__(256) void gemm_xn_kv(const float* __restrict__ kv_w) {
    gemm_body(G_XN, kv_w, nullptr, G_KV, B_ * N_, 2 * C_, C_, 0);
}
__global__ __launch_bounds__(256) void gemm_qc1_hb(const float* __restrict__ w,
                                                   const float* __restrict__ b) {
    gemm_body(G_QC1, w, b, G_HB, B_ * NT_, 2 * C_, C_, 1);
}
__global__ __launch_bounds__(256) void gemm_hb_qc2(const float* __restrict__ w,
                                                   const float* __restrict__ b) {
    gemm_body(G_HB, w, b, G_QC2, B_ * NT_, C_, 2 * C_, 0);
}
__global__ __launch_bounds__(256) void gemm_av_out(const float* __restrict__ w,
                                                   const float* __restrict__ b,
                                                   float* __restrict__ out) {
    gemm_body(G_AV, w, b, out, B_ * NT_, C_, C_, 0);
}

// round 3
// speedup vs baseline: 1.0967x; 1.0967x over previous
#include <cuda_runtime.h>
#include <cstdint>
#include <math.h>

#define B_   32
#define N_   3136
#define C_   384
#define H_   8
#define HD_  48
#define NT_  196
#define EPS_ 1e-6f
#define SCALE_ 0.14433756729740643f   /* 1/sqrt(48) */

typedef unsigned long long ull;

// ---------------------------------------------------------------------------
// Scratch: one big static device buffer (no runtime allocation).
// ---------------------------------------------------------------------------
#define XN_OFF   ((size_t)0)
#define KV_OFF   (XN_OFF  + (size_t)B_*N_*C_)
#define QC1_OFF  (KV_OFF  + (size_t)B_*N_*2*C_)
#define HB_OFF   (QC1_OFF + (size_t)B_*NT_*C_)
#define QC2_OFF  (HB_OFF  + (size_t)B_*NT_*2*C_)
#define AV_OFF   (QC2_OFF + (size_t)B_*NT_*C_)
#define CENT_OFF (AV_OFF  + (size_t)B_*NT_*C_)
#define TOTAL_F  (CENT_OFF + (size_t)B_*NT_)

__device__ __align__(128) float g_scratch[TOTAL_F];

#define G_XN   (g_scratch + XN_OFF)
#define G_KV   (g_scratch + KV_OFF)
#define G_QC1  (g_scratch + QC1_OFF)
#define G_HB   (g_scratch + HB_OFF)
#define G_QC2  (g_scratch + QC2_OFF)
#define G_AV   (g_scratch + AV_OFF)
#define G_CENT ((int*)(g_scratch + CENT_OFF))

// ---------------------------------------------------------------------------
// f32x2 packed helpers
// ---------------------------------------------------------------------------
__device__ __forceinline__ ull pack2(float x, float y) {
    ull r; asm("mov.b64 %0, {%1,%2};" : "=l"(r) : "f"(x), "f"(y)); return r;
}
__device__ __forceinline__ float2 unpack2(ull v) {
    float2 f; asm("mov.b64 {%0,%1}, %2;" : "=f"(f.x), "=f"(f.y) : "l"(v)); return f;
}
__device__ __forceinline__ void fma2(ull& d, ull a, ull b) {
    asm("fma.rn.f32x2 %0, %1, %2, %0;" : "+l"(d) : "l"(a), "l"(b));
}

__device__ __forceinline__ float gelu_f(float x) {
    return 0.5f * x * (1.0f + erff(x * 0.70710678118654752f));
}

// ---------------------------------------------------------------------------
// K0: LayerNorm. One block per row, 128 threads, 3 elems/thread.
// ---------------------------------------------------------------------------
__global__ void ln_kernel(const float* __restrict__ x,
                          const float* __restrict__ w,
                          const float* __restrict__ b) {
    int row = blockIdx.x;
    const float* xr = x + (size_t)row * C_;
    int tid = threadIdx.x;
    float v[3];
    float s = 0.f, sq = 0.f;
#pragma unroll
    for (int i = 0; i < 3; i++) {
        v[i] = xr[tid + 128 * i];
        s += v[i]; sq += v[i] * v[i];
    }
#pragma unroll
    for (int o = 16; o; o >>= 1) {
        s  += __shfl_xor_sync(0xffffffffu, s, o);
        sq += __shfl_xor_sync(0xffffffffu, sq, o);
    }
    __shared__ float ss[4], ssq[4];
    if ((tid & 31) == 0) { ss[tid >> 5] = s; ssq[tid >> 5] = sq; }
    __syncthreads();
    s  = ss[0] + ss[1] + ss[2] + ss[3];
    sq = ssq[0] + ssq[1] + ssq[2] + ssq[3];
    float mu = s * (1.0f / C_);
    float var = sq * (1.0f / C_) - mu * mu;
    float rstd = rsqrtf(var + EPS_);
    float* orow = G_XN + (size_t)row * C_;
#pragma unroll
    for (int i = 0; i < 3; i++) {
        int c = tid + 128 * i;
        orow[c] = (v[i] - mu) * rstd * w[c] + b[c];
    }
}

// ---------------------------------------------------------------------------
// GEMM: C[M,Nn] = A[M,K] @ W[Nn,K]^T (+bias)(+gelu)
// 128x128x16 tile, 256 threads, 8x8 microtile, f32x2 math,
// register-staged double-buffered smem (one barrier per BK).
// ---------------------------------------------------------------------------
#define BM 128
#define BN 128
#define BK 16

__device__ __forceinline__
void gemm_body(const float* __restrict__ A, const float* __restrict__ W,
               const float* __restrict__ bias, float* __restrict__ Cm,
               int M, int Nn, int K, int epi) {
    __shared__ __align__(16) float As[2][BK][BM];
    __shared__ __align__(16) float Bs[2][BK][BN];
    int tid = threadIdx.x;
    int tx = tid & 15, ty = tid >> 4;
    int m0 = blockIdx.y * BM, n0 = blockIdx.x * BN;

    // Global-load mapping: 2 threads per row, 8 cols (2x float4) per thread.
    int lr = tid >> 1;
    int lc = (tid & 1) * 8;
    const float* Aptr = A + (size_t)(m0 + lr) * K + lc;
    const float* Wptr = W + (size_t)(n0 + lr) * K + lc;

    ull acc[8][4];
#pragma unroll
    for (int i = 0; i < 8; i++)
#pragma unroll
        for (int j = 0; j < 4; j++) acc[i][j] = 0ull;

    // Prologue: tile 0 -> smem buffer 0
    float4 a0 = *(const float4*)(Aptr + 0);
    float4 a1 = *(const float4*)(Aptr + 4);
    float4 b0 = *(const float4*)(Wptr + 0);
    float4 b1 = *(const float4*)(Wptr + 4);
    As[0][lc + 0][lr] = a0.x; As[0][lc + 1][lr] = a0.y;
    As[0][lc + 2][lr] = a0.z; As[0][lc + 3][lr] = a0.w;
    As[0][lc + 4][lr] = a1.x; As[0][lc + 5][lr] = a1.y;
    As[0][lc + 6][lr] = a1.z; As[0][lc + 7][lr] = a1.w;
    Bs[0][lc + 0][lr] = b0.x; Bs[0][lc + 1][lr] = b0.y;
    Bs[0][lc + 2][lr] = b0.z; Bs[0][lc + 3][lr] = b0.w;
    Bs[0][lc + 4][lr] = b1.x; Bs[0][lc + 5][lr] = b1.y;
    Bs[0][lc + 6][lr] = b1.z; Bs[0][lc + 7][lr] = b1.w;
    __syncthreads();

    int nk = K / BK;
    for (int kt = 0; kt < nk; kt++) {
        int cur = kt & 1;
        if (kt + 1 < nk) {
            const float* Ap = Aptr + (kt + 1) * BK;
            const float* Wp = Wptr + (kt + 1) * BK;
            a0 = *(const float4*)(Ap + 0);
            a1 = *(const float4*)(Ap + 4);
            b0 = *(const float4*)(Wp + 0);
            b1 = *(const float4*)(Wp + 4);
        }
#pragma unroll
        for (int kk = 0; kk < BK; kk++) {
            float4 av0 = *(const float4*)&As[cur][kk][ty * 8];
            float4 av1 = *(const float4*)&As[cur][kk][ty * 8 + 4];
            float4 bv0 = *(const float4*)&Bs[cur][kk][tx * 8];
            float4 bv1 = *(const float4*)&Bs[cur][kk][tx * 8 + 4];
            ull bp0 = pack2(bv0.x, bv0.y);
            ull bp1 = pack2(bv0.z, bv0.w);
            ull bp2 = pack2(bv1.x, bv1.y);
            ull bp3 = pack2(bv1.z, bv1.w);
            float am[8] = {av0.x, av0.y, av0.z, av0.w,
                           av1.x, av1.y, av1.z, av1.w};
#pragma unroll
            for (int i = 0; i < 8; i++) {
                ull ap = pack2(am[i], am[i]);
                fma2(acc[i][0], ap, bp0);
                fma2(acc[i][1], ap, bp1);
                fma2(acc[i][2], ap, bp2);
                fma2(acc[i][3], ap, bp3);
            }
        }
        if (kt + 1 < nk) {
            int nxt = 1 - cur;
            As[nxt][lc + 0][lr] = a0.x; As[nxt][lc + 1][lr] = a0.y;
            As[nxt][lc + 2][lr] = a0.z; As[nxt][lc + 3][lr] = a0.w;
            As[nxt][lc + 4][lr] = a1.x; As[nxt][lc + 5][lr] = a1.y;
            As[nxt][lc + 6][lr] = a1.z; As[nxt][lc + 7][lr] = a1.w;
            Bs[nxt][lc + 0][lr] = b0.x; Bs[nxt][lc + 1][lr] = b0.y;
            Bs[nxt][lc + 2][lr] = b0.z; Bs[nxt][lc + 3][lr] = b0.w;
            Bs[nxt][lc + 4][lr] = b1.x; Bs[nxt][lc + 5][lr] = b1.y;
            Bs[nxt][lc + 6][lr] = b1.z; Bs[nxt][lc + 7][lr] = b1.w;
            __syncthreads();
        }
    }

    int gn = n0 + tx * 8;
    float bb[8];
#pragma unroll
    for (int j = 0; j < 8; j++) bb[j] = bias ? bias[gn + j] : 0.f;
#pragma unroll
    for (int i = 0; i < 8; i++) {
        int gm = m0 + ty * 8 + i;
        float o[8];
#pragma unroll
        for (int j = 0; j < 4; j++) {
            float2 c = unpack2(acc[i][j]);
            o[2 * j] = c.x + bb[2 * j];
            o[2 * j + 1] = c.y + bb[2 * j + 1];
        }
        if (epi == 1) {
#pragma unroll
            for (int j = 0; j < 8; j++) o[j] = gelu_f(o[j]);
        }
        float4 w0 = {o[0], o[1], o[2], o[3]};
        float4 w1 = {o[4], o[5], o[6], o[7]};
        *(float4*)(Cm + (size_t)gm * Nn + gn) = w0;
        *(float4*)(Cm + (size_t)gm * Nn + gn + 4) = w1;
    }
}

__global__ __launch_bounds__(256, 2) void gemm_xn_kv(const float* __restrict__ kv_w) {
    gemm_body(G_XN, kv_w, nullptr, G_KV, B_ * N_, 2 * C_, C_, 0);
}
__global__ __launch_bounds__(256, 2) void gemm_qc1_hb(const float* __restrict__ w,
                                                      const float* __restrict__ b) {
    gemm_body(G_QC1, w, b, G_HB, B_ * NT_, 2 * C_, C_, 1);
}
__global__ __launch_bounds__(256, 2) void gemm_hb_qc2(const float* __restrict__ w,
                                                      const float* __restrict__ b) {
    gemm_body(G_HB, w, b, G_QC2, B_ * NT_, C_, 2 * C_, 0);
}
__global__ __launch_bounds__(256, 2) void gemm_av_out(const float* __restrict__ w,
                                                      const float* __restrict__ b,
                                                      float* __restrict__ out) {
    gemm_body(G_AV, w, b, out, B_ * NT_, C_, C_, 0);
}

// ---------------------------------------------------------------------------
// K2: attn1 + q_cond1. One block per (b,h). Stage q/k_sub/v_sub in dyn smem.
// ---------------------------------------------------------------------------
#define ATTN1_SMEM (3 * NT_ * HD_ * 4)   /* 112896 bytes */

__global__ __launch_bounds__(256)
void attn1_kernel(const float* __restrict__ qg, const int* __restrict__ idx_sub) {
    extern __shared__ float sh[];
    float* qs = sh;
    float* ks = sh + NT_ * HD_;
    float* vs = sh + 2 * NT_ * HD_;
    int b = blockIdx.x >> 3;
    int h = blockIdx.x & 7;
    int tid = threadIdx.x;
    const float* kv = G_KV;

    for (int i = tid; i < NT_ * HD_; i += 256) {
        int n = i / HD_, d = i % HD_;
        qs[i] = qg[((size_t)n * H_ + h) * HD_ + d];
        int src = idx_sub[n];
        const float* kvrow = kv + ((size_t)b * N_ + src) * (2 * C_) + h * HD_ + d;
        ks[i] = kvrow[0];
        vs[i] = kvrow[C_];
    }
    __syncthreads();

    int m = tid;
    if (m < NT_) {
        float sc[NT_];
        float mx = -1e30f;
        const float* qm = qs + m * HD_;
        for (int n = 0; n < NT_; n++) {
            const float* kn = ks + n * HD_;
            float s = 0.f;
#pragma unroll
            for (int d = 0; d < HD_; d++) s += qm[d] * kn[d];
            s *= SCALE_;
            sc[n] = s;
            mx = fmaxf(mx, s);
        }
        float sum = 0.f;
        for (int n = 0; n < NT_; n++) {
            float e = expf(sc[n] - mx);
            sc[n] = e; sum += e;
        }
        float inv = 1.0f / sum;
        float accv[HD_];
#pragma unroll
        for (int d = 0; d < HD_; d++) accv[d] = 0.f;
        for (int n = 0; n < NT_; n++) {
            float wgt = sc[n];
            const float* vn = vs + n * HD_;
#pragma unroll
            for (int d = 0; d < HD_; d++) accv[d] += wgt * vn[d];
        }
        float* orow = G_QC1 + ((size_t)b * NT_ + m) * C_ + h * HD_;
#pragma unroll
        for (int d = 0; d < HD_; d++) orow[d] = accv[d] * inv;
    }
}

// ---------------------------------------------------------------------------
// K5: attn2 mean-over-heads + argmax (fp32-exact; tie rule preserved).
// ---------------------------------------------------------------------------
#define MCH 7
__global__ __launch_bounds__(256)
void attn2_kernel(const int* __restrict__ idxs) {
    int b = blockIdx.x / 28;
    int m0 = (blockIdx.x % 28) * MCH;
    __shared__ float qsh[MCH * C_];
    __shared__ float krow[C_];
    __shared__ int sIdxs[NT_];
    int tid = threadIdx.x;
    const float* kv = G_KV;
    for (int i = tid; i < MCH * C_; i += 256)
        qsh[i] = G_QC2[((size_t)b * NT_ + m0) * C_ + i];
    for (int i = tid; i < NT_; i += 256) sIdxs[i] = idxs[i];
    int warp = tid >> 5, lane = tid & 31;
    float best = -1e30f;
    int bestn = 0;
    __syncthreads();
    for (int n = 0; n < NT_; n++) {
        __syncthreads();
        for (int i = tid; i < C_; i += 256)
            krow[i] = kv[((size_t)b * N_ + sIdxs[n]) * (2 * C_) + i];
        __syncthreads();
        if (warp < MCH) {
            const float* qm = qsh + warp * C_;
            float p = 0.f;
#pragma unroll
            for (int j = 0; j < 12; j++) p += qm[lane + 32 * j] * krow[lane + 32 * j];
#pragma unroll
            for (int o = 16; o; o >>= 1) p += __shfl_xor_sync(0xffffffffu, p, o);
            if (p > best) { best = p; bestn = n; }
        }
    }
    if (warp < MCH && lane == 0)
        G_CENT[(size_t)b * NT_ + m0 + warp] = sIdxs[bestn];
}

// ---------------------------------------------------------------------------
// K6: masked attn3 (sparse over deduped adjusted-index set).
// ---------------------------------------------------------------------------
__global__ __launch_bounds__(256)
void attn3_kernel() {
    int bm = blockIdx.x;
    int b = bm / NT_;
    __shared__ unsigned int bmap[N_ / 32];
    __shared__ int sIdx[169];
    __shared__ int cnt;
    __shared__ float sQ[C_];
    __shared__ float sS[H_][169];
    int tid = threadIdx.x;
    const float* kv = G_KV;
    if (tid < N_ / 32) bmap[tid] = 0u;
    if (tid == 0) cnt = 0;
    __syncthreads();
    int ci = G_CENT[bm];
    if (tid < 169) {
        int row = tid / 13 - 6;
        int col = tid % 13 - 6;
        int adj = ci + (col - 56 * row);
        adj = max(0, min(N_ - 1, adj));
        atomicOr(&bmap[adj >> 5], 1u << (adj & 31));
    }
    for (int i = tid; i < C_; i += 256)
        sQ[i] = G_QC2[(size_t)bm * C_ + i] * SCALE_;
    __syncthreads();
    if (tid < N_ / 32) {
        unsigned int w = bmap[tid];
        if (w) {
            int base = atomicAdd(&cnt, __popc(w));
            int off = 0;
            while (w) {
                int bit = __ffs(w) - 1;
                w &= w - 1;
                sIdx[base + off] = (tid << 5) + bit;
                off++;
            }
        }
    }
    __syncthreads();
    int count = cnt;
    int h = tid >> 5, lane = tid & 31;
    const float* qh = sQ + h * HD_;
    float mx = -1e30f;
    for (int e = 0; e < count; e++) {
        const float* kr = kv + ((size_t)b * N_ + sIdx[e]) * (2 * C_) + h * HD_;
        float p = kr[lane] * qh[lane];
        if (lane < 16) p += kr[lane + 32] * qh[lane + 32];
#pragma unroll
        for (int o = 16; o; o >>= 1) p += __shfl_xor_sync(0xffffffffu, p, o);
        if (lane == 0) sS[h][e] = p;
        mx = fmaxf(mx, p);
    }
    __syncwarp();
    float sum = 0.f;
    for (int e = lane; e < count; e += 32) {
        float ee = expf(sS[h][e] - mx);
        sS[h][e] = ee;
        sum += ee;
    }
#pragma unroll
    for (int o = 16; o; o >>= 1) sum += __shfl_xor_sync(0xffffffffu, sum, o);
    float inv = 1.0f / sum;
    __syncwarp();
    float a0 = 0.f, a1 = 0.f;
    for (int e = 0; e < count; e++) {
        float wgt = sS[h][e];
        const float* vr = kv + ((size_t)b * N_ + sIdx[e]) * (2 * C_) + C_ + h * HD_;
        a0 += wgt * vr[lane];
        if (lane < 16) a1 += wgt * vr[lane + 32];
    }
    float* orow = G_AV + (size_t)bm * C_ + h * HD_;
    orow[lane] = a0 * inv;
    if (lane < 16) orow[lane + 32] = a1 * inv;
}

// ---------------------------------------------------------------------------
// Launch: kernel launches ONLY.
// ---------------------------------------------------------------------------
extern "C" void kernel_launch(void* const* d_in, const int* in_sizes, int n_in,
                              void* d_out, int out_size) {
    const float* x      = (const float*)d_in[0];
    const float* q      = (const float*)d_in[1];
    const float* kv_w   = (const float*)d_in[2];
    const float* proj_w = (const float*)d_in[3];
    const float* proj_b = (const float*)d_in[4];
    const float* ln_w   = (const float*)d_in[5];
    const float* ln_b   = (const float*)d_in[6];
    const float* fc1_w  = (const float*)d_in[7];
    const float* fc1_b  = (const float*)d_in[8];
    const float* fc2_w  = (const float*)d_in[9];
    const float* fc2_b  = (const float*)d_in[10];
    const int* idx_sub  = (const int*)d_in[11];
    const int* idxs     = (const int*)d_in[12];
    float* out = (float*)d_out;

    cudaFuncSetAttribute(attn1_kernel,
                         cudaFuncAttributeMaxDynamicSharedMemorySize, ATTN1_SMEM);

    // K0: LayerNorm -> G_XN
    ln_kernel<<<B_ * N_, 128>>>(x, ln_w, ln_b);

    // K1: KV projection (dominant GEMM, fp32-exact)
    {
        dim3 g(2 * C_ / BN, (B_ * N_) / BM);
        gemm_xn_kv<<<g, 256>>>(kv_w);
    }

    // K2: attn1 -> G_QC1
    attn1_kernel<<<B_ * H_, 256, ATTN1_SMEM>>>(q, idx_sub);

    // K3: fc1 + gelu -> G_HB
    {
        dim3 g(2 * C_ / BN, (B_ * NT_) / BM);
        gemm_qc1_hb<<<g, 256>>>(fc1_w, fc1_b);
    }
    // K4: fc2 -> G_QC2
    {
        dim3 g(C_ / BN, (B_ * NT_) / BM);
        gemm_hb_qc2<<<g, 256>>>(fc2_w, fc2_b);
    }

    // K5: attn2 + argmax -> G_CENT
    attn2_kernel<<<B_ * 28, 256>>>(idxs);

    // K6: sparse masked attn3 -> G_AV
    attn3_kernel<<<B_ * NT_, 256>>>();

    // K7: output projection -> d_out
    {
        dim3 g(C_ / BN, (B_ * NT_) / BM);
        gemm_av_out<<<g, 256>>>(proj_w, proj_b, out);
    }
}